// round 7
// baseline (speedup 1.0000x reference)
#include <cuda_runtime.h>
#include <cstdint>

// Chamfer loss. B=16, N=4096, C=6 (first 3 used).
// d(i,j) = |q_i|^2 + [ |r_j|^2 - 2 q_i . r_j ]
// R5: j-split. 128 CTAs x 512 thr, IPT=4 queries/thread, each CTA covers one
// (dir,batch,qtile,jhalf); per-query partial (rq+min over 2048 refs) written to
// g_part[q][half]; k_reduce sums min(half0,half1) and finalizes.

#define BATCH 16
#define NPTS  4096
#define CSTR  6
#define THREADS 512
#define IPT 4
#define JT  2048          // refs per CTA (one smem tile, no tile loop)
#define J2  (JT / 2)
#define GRID 128

#define NQ_TOTAL (2 * BATCH * NPTS)       // 131072 queries (both directions)

__device__ float        g_part[NQ_TOTAL * 2];  // [query][jhalf], fully overwritten each launch
__device__ float        g_acc;                  // zero-init; reset by reduce finalizer
__device__ unsigned int g_count;                // zero-init; reset by reduce finalizer

__device__ __forceinline__ unsigned long long pk2(float lo, float hi) {
    unsigned long long r;
    asm("mov.b64 %0, {%1, %2};" : "=l"(r) : "f"(lo), "f"(hi));
    return r;
}
__device__ __forceinline__ unsigned long long fma2(unsigned long long a,
                                                   unsigned long long b,
                                                   unsigned long long c) {
    unsigned long long d;
    asm("fma.rn.f32x2 %0, %1, %2, %3;" : "=l"(d) : "l"(a), "l"(b), "l"(c));
    return d;
}
__device__ __forceinline__ void upk2(unsigned long long v, float& lo, float& hi) {
    asm("mov.b64 {%0, %1}, %2;" : "=f"(lo), "=f"(hi) : "l"(v));
}

__global__ void __launch_bounds__(THREADS)
k_chamfer(const float* __restrict__ x, const float* __restrict__ y) {
    __shared__ ulonglong2 s_a[J2];   // {-2rx pair}, {-2ry pair}
    __shared__ ulonglong2 s_b[J2];   // {-2rz pair}, {rr pair}

    const int bid   = blockIdx.x;          // 0..127
    const int jhalf = bid & 1;
    const int qtile = (bid >> 1) & 1;
    const int b     = (bid >> 2) & 15;
    const int dir   = bid >> 6;            // 0: q=x,r=y ; 1: q=y,r=x

    const float* q  = dir ? y : x;
    const float* r  = dir ? x : y;
    const float* qb = q + (size_t)b * NPTS * CSTR;
    const float* rb = r + (size_t)b * NPTS * CSTR + (size_t)jhalf * JT * CSTR;

    const int tid = threadIdx.x;

    // stage prescaled ref half-tile into smem
    for (int j = tid; j < J2; j += THREADS) {
        const float* p = rb + (size_t)(2 * j) * CSTR;
        float a0 = p[0], b0 = p[1], c0 = p[2];
        float a1 = p[6], b1 = p[7], c1 = p[8];
        float rr0 = fmaf(a0, a0, fmaf(b0, b0, c0 * c0));
        float rr1 = fmaf(a1, a1, fmaf(b1, b1, c1 * c1));
        ulonglong2 va, vb;
        va.x = pk2(-2.0f * a0, -2.0f * a1);
        va.y = pk2(-2.0f * b0, -2.0f * b1);
        vb.x = pk2(-2.0f * c0, -2.0f * c1);
        vb.y = pk2(rr0, rr1);
        s_a[j] = va;
        s_b[j] = vb;
    }

    unsigned long long qx2[IPT], qy2[IPT], qz2[IPT];
    float rq[IPT], mnl[IPT], mnh[IPT];
    const int i0 = qtile * (THREADS * IPT) + tid * IPT;
#pragma unroll
    for (int k = 0; k < IPT; k++) {
        const float* p = qb + (size_t)(i0 + k) * CSTR;
        float a = p[0], bb = p[1], c = p[2];
        rq[k]  = fmaf(a, a, fmaf(bb, bb, c * c));
        qx2[k] = pk2(a, a);
        qy2[k] = pk2(bb, bb);
        qz2[k] = pk2(c, c);
        mnl[k] = 3.4e38f;
        mnh[k] = 3.4e38f;
    }
    __syncthreads();

#pragma unroll 4
    for (int j = 0; j < J2; j++) {
        ulonglong2 va = s_a[j];
        ulonglong2 vb = s_b[j];
#pragma unroll
        for (int k = 0; k < IPT; k++) {
            unsigned long long d =
                fma2(qx2[k], va.x, fma2(qy2[k], va.y, fma2(qz2[k], vb.x, vb.y)));
            float dl, dh;
            upk2(d, dl, dh);
            mnl[k] = fminf(mnl[k], dl);
            mnh[k] = fminf(mnh[k], dh);
        }
    }

    // write per-query partials: value = rq + min over this j-half
    const int qg = (dir * BATCH + b) * NPTS + i0;   // global query index
#pragma unroll
    for (int k = 0; k < IPT; k++) {
        g_part[(size_t)(qg + k) * 2 + jhalf] = rq[k] + fminf(mnl[k], mnh[k]);
    }
}

#define RGRID   128
#define RTHREADS 256
// each thread: 4 queries -> 8 floats = 2 float4 loads

__global__ void __launch_bounds__(RTHREADS)
k_reduce(float* __restrict__ out) {
    __shared__ float ws[RTHREADS / 32];
    const int tid  = threadIdx.x;
    const int base = (blockIdx.x * RTHREADS + tid) * 4;   // query base

    const float4* p = (const float4*)g_part;              // p[i] = 2 queries
    float4 v0 = p[base / 2];
    float4 v1 = p[base / 2 + 1];
    float s = fminf(v0.x, v0.y) + fminf(v0.z, v0.w)
            + fminf(v1.x, v1.y) + fminf(v1.z, v1.w);

#pragma unroll
    for (int o = 16; o > 0; o >>= 1)
        s += __shfl_xor_sync(0xffffffffu, s, o);
    if ((tid & 31) == 0) ws[tid >> 5] = s;
    __syncthreads();

    if (tid == 0) {
        float t = 0.0f;
#pragma unroll
        for (int w = 0; w < RTHREADS / 32; w++) t += ws[w];
        atomicAdd(&g_acc, t);
        __threadfence();
        unsigned int arrived = atomicAdd(&g_count, 1u);
        if (arrived == RGRID - 1) {
            __threadfence();
            float total = *((volatile float*)&g_acc);
            out[0] = total * (1.0f / (float)(BATCH * NPTS));
            g_acc   = 0.0f;
            g_count = 0u;
        }
    }
}

extern "C" void kernel_launch(void* const* d_in, const int* in_sizes, int n_in,
                              void* d_out, int out_size) {
    const float* x = (const float*)d_in[0];
    const float* y = (const float*)d_in[1];
    float* out = (float*)d_out;
    (void)in_sizes; (void)n_in; (void)out_size;

    k_chamfer<<<GRID, THREADS>>>(x, y);
    k_reduce<<<RGRID, RTHREADS>>>(out);
}

// round 10
// speedup vs baseline: 1.0770x; 1.0770x over previous
#include <cuda_runtime.h>
#include <cstdint>

// Chamfer loss, symmetric single pass: each of the 268M unique (i,j) distances
// is computed ONCE and feeds both rowmin (min over j -> x side) and colmin
// (min over i -> y side).
//
// CTA = (batch, i-eighth of 512, j-half of 2048). 8 warps.
//  - lane owns 8 consecutive j: prescaled (-2y0,-2y1,-2y2,ry) packed f32x2 in
//    registers, plus 8 register colmins.
//  - CTA sweeps its 512-i x-tile from smem (packed broadcast pairs).
//  - per i: lane makes t = min over its 8 j of d(i,j); t stashed to a per-warp
//    smem buffer; every 16 i-steps a transposed read + tree + 1 shfl produces
//    the warp-rowmin for 16 i's, written coalesced to g_rowpart.
// k_reduce: final row = min of 16 slices, col = min of 8 slices; mean.

#define BATCH 16
#define NPTS  4096
#define CSTR  6
#define THREADS 256
#define NW    8
#define I8    512
#define JH    2048
#define GRID  (BATCH * 8 * 2)     // 256 CTAs

#define NQ    (BATCH * NPTS)      // 65536 per side

__device__ float        g_rowpart[16 * NQ];   // [slice=jh*8+w][b*4096+i]
__device__ float        g_colpart[8 * NQ];    // [slice=i8][b*4096+j]
__device__ float        g_acc;
__device__ unsigned int g_count;

typedef unsigned long long ull;

__device__ __forceinline__ ull pk2(float lo, float hi) {
    ull r; asm("mov.b64 %0, {%1, %2};" : "=l"(r) : "f"(lo), "f"(hi)); return r;
}
__device__ __forceinline__ ull fma2(ull a, ull b, ull c) {
    ull d; asm("fma.rn.f32x2 %0, %1, %2, %3;" : "=l"(d) : "l"(a), "l"(b), "l"(c)); return d;
}
__device__ __forceinline__ ull add2(ull a, ull b) {
    ull d; asm("add.rn.f32x2 %0, %1, %2;" : "=l"(d) : "l"(a), "l"(b)); return d;
}
__device__ __forceinline__ void upk2(ull v, float& lo, float& hi) {
    asm("mov.b64 {%0, %1}, %2;" : "=f"(lo), "=f"(hi) : "l"(v));
}

__global__ void __launch_bounds__(THREADS)
k_main(const float* __restrict__ x, const float* __restrict__ y) {
    __shared__ ulonglong2 sx[I8][2];        // 16 KB: {(x0,x0),(x1,x1)},{(x2,x2),(rx,rx)}
    __shared__ float      buf[NW][16][36];  // 18.4 KB: per-warp rowmin staging

    const int bid = blockIdx.x;
    const int jh  = bid & 1;
    const int i8  = (bid >> 1) & 7;
    const int b   = bid >> 4;

    const float* xb = x + (size_t)b * NPTS * CSTR;
    const float* yb = y + (size_t)b * NPTS * CSTR;

    const int tid  = threadIdx.x;
    const int w    = tid >> 5;
    const int lane = tid & 31;

    // stage packed-broadcast x tile
    const int ibase = i8 * I8;
    for (int t = tid; t < I8; t += THREADS) {
        const float* p = xb + (size_t)(ibase + t) * CSTR;
        float a = p[0], c = p[1], e = p[2];
        float rx = fmaf(a, a, fmaf(c, c, e * e));
        ulonglong2 v0, v1;
        v0.x = pk2(a, a);  v0.y = pk2(c, c);
        v1.x = pk2(e, e);  v1.y = pk2(rx, rx);
        sx[t][0] = v0;  sx[t][1] = v1;
    }

    // this lane's 8 j-points, prescaled + packed over j
    ull ax[4], ay[4], az[4], ryp[4];
    const int j0 = jh * JH + w * 256 + lane * 8;
#pragma unroll
    for (int p = 0; p < 4; p++) {
        const float* pj = yb + (size_t)(j0 + 2 * p) * CSTR;
        float a0 = pj[0], b0 = pj[1], c0 = pj[2];
        float a1 = pj[6], b1 = pj[7], c1 = pj[8];
        float rr0 = fmaf(a0, a0, fmaf(b0, b0, c0 * c0));
        float rr1 = fmaf(a1, a1, fmaf(b1, b1, c1 * c1));
        ax[p]  = pk2(-2.0f * a0, -2.0f * a1);
        ay[p]  = pk2(-2.0f * b0, -2.0f * b1);
        az[p]  = pk2(-2.0f * c0, -2.0f * c1);
        ryp[p] = pk2(rr0, rr1);
    }

    float cm[8];
#pragma unroll
    for (int k = 0; k < 8; k++) cm[k] = 3.4e38f;

    __syncthreads();

    float* rowp = g_rowpart + (size_t)(jh * 8 + w) * NQ + b * NPTS + ibase;

    for (int blk = 0; blk < I8 / 16; blk++) {
#pragma unroll 4
        for (int s = 0; s < 16; s++) {
            const int i = blk * 16 + s;
            ulonglong2 v0 = sx[i][0];
            ulonglong2 v1 = sx[i][1];
            float e0, e1, e2, e3, e4, e5, e6, e7;
            upk2(add2(fma2(v0.x, ax[0], fma2(v0.y, ay[0], fma2(v1.x, az[0], ryp[0]))), v1.y), e0, e1);
            upk2(add2(fma2(v0.x, ax[1], fma2(v0.y, ay[1], fma2(v1.x, az[1], ryp[1]))), v1.y), e2, e3);
            upk2(add2(fma2(v0.x, ax[2], fma2(v0.y, ay[2], fma2(v1.x, az[2], ryp[2]))), v1.y), e4, e5);
            upk2(add2(fma2(v0.x, ax[3], fma2(v0.y, ay[3], fma2(v1.x, az[3], ryp[3]))), v1.y), e6, e7);

            cm[0] = fminf(cm[0], e0); cm[1] = fminf(cm[1], e1);
            cm[2] = fminf(cm[2], e2); cm[3] = fminf(cm[3], e3);
            cm[4] = fminf(cm[4], e4); cm[5] = fminf(cm[5], e5);
            cm[6] = fminf(cm[6], e6); cm[7] = fminf(cm[7], e7);

            float t = fminf(fminf(fminf(e0, e1), fminf(e2, e3)),
                            fminf(fminf(e4, e5), fminf(e6, e7)));
            buf[w][s][lane] = t;
        }
        __syncwarp();
        {
            // transposed reduce: lane (r,h) reads buf[w][r][h*16..h*16+15]
            const int r = lane & 15, h = lane >> 4;
            const float* rowv = &buf[w][r][h * 16];
            float4 a0 = *(const float4*)(rowv + 0);
            float4 a1 = *(const float4*)(rowv + 4);
            float4 a2 = *(const float4*)(rowv + 8);
            float4 a3 = *(const float4*)(rowv + 12);
            float m = fminf(fminf(fminf(a0.x, a0.y), fminf(a0.z, a0.w)),
                            fminf(fminf(a1.x, a1.y), fminf(a1.z, a1.w)));
            m = fminf(m, fminf(fminf(fminf(a2.x, a2.y), fminf(a2.z, a2.w)),
                               fminf(fminf(a3.x, a3.y), fminf(a3.z, a3.w))));
            m = fminf(m, __shfl_xor_sync(0xffffffffu, m, 16));
            if (h == 0) rowp[blk * 16 + r] = m;
        }
        __syncwarp();
    }

    // col partials: contiguous 8 floats per lane -> 2 STG.128
    float* colp = g_colpart + (size_t)i8 * NQ + b * NPTS + j0;
    float4 c0 = make_float4(cm[0], cm[1], cm[2], cm[3]);
    float4 c1 = make_float4(cm[4], cm[5], cm[6], cm[7]);
    *(float4*)(colp + 0) = c0;
    *(float4*)(colp + 4) = c1;
}

#define RGRID 128
#define RTHREADS 256

__device__ __forceinline__ float4 vmin4(float4 a, float4 b) {
    return make_float4(fminf(a.x, b.x), fminf(a.y, b.y),
                       fminf(a.z, b.z), fminf(a.w, b.w));
}

__global__ void __launch_bounds__(RTHREADS)
k_reduce(float* __restrict__ out) {
    __shared__ float ws[RTHREADS / 32];
    const int tid = threadIdx.x;
    const int cta = blockIdx.x;

    float s = 0.0f;
    if (cta < 64) {
        const int g = (cta * RTHREADS + tid) * 4;
        float4 m = *(const float4*)&g_rowpart[g];
#pragma unroll
        for (int sl = 1; sl < 16; sl++)
            m = vmin4(m, *(const float4*)&g_rowpart[(size_t)sl * NQ + g]);
        s = (m.x + m.y) + (m.z + m.w);
    } else {
        const int g = ((cta - 64) * RTHREADS + tid) * 4;
        float4 m = *(const float4*)&g_colpart[g];
#pragma unroll
        for (int sl = 1; sl < 8; sl++)
            m = vmin4(m, *(const float4*)&g_colpart[(size_t)sl * NQ + g]);
        s = (m.x + m.y) + (m.z + m.w);
    }

#pragma unroll
    for (int o = 16; o > 0; o >>= 1)
        s += __shfl_xor_sync(0xffffffffu, s, o);
    if ((tid & 31) == 0) ws[tid >> 5] = s;
    __syncthreads();

    if (tid == 0) {
        float t = 0.0f;
#pragma unroll
        for (int u = 0; u < RTHREADS / 32; u++) t += ws[u];
        atomicAdd(&g_acc, t);
        __threadfence();
        unsigned int arrived = atomicAdd(&g_count, 1u);
        if (arrived == RGRID - 1) {
            __threadfence();
            float total = *((volatile float*)&g_acc);
            out[0] = total * (1.0f / (float)NQ);
            g_acc   = 0.0f;
            g_count = 0u;
        }
    }
}

extern "C" void kernel_launch(void* const* d_in, const int* in_sizes, int n_in,
                              void* d_out, int out_size) {
    const float* x = (const float*)d_in[0];
    const float* y = (const float*)d_in[1];
    float* out = (float*)d_out;
    (void)in_sizes; (void)n_in; (void)out_size;

    k_main<<<GRID, THREADS>>>(x, y);
    k_reduce<<<RGRID, RTHREADS>>>(out);
}